// round 3
// baseline (speedup 1.0000x reference)
#include <cuda_runtime.h>
#include <cuda_bf16.h>

#define KDIM 8
static const int MAXN = 100000;
static const int MAXE = 3200000;

// ---- scratch (device globals; no cudaMalloc allowed) ----
__device__ int    g_count[MAXN];          // per-dst degree histogram
__device__ int    g_rank[MAXE];           // rank of edge within its dst bin
__device__ int    g_off[MAXN + 1];        // bin offsets (exclusive scan)
__device__ int    g_blocklocal[MAXN];     // exclusive scan within scan-block
__device__ int    g_blocksum[128];        // per-scan-block totals (<=98 used)
__device__ int    g_blockbase[128];       // exclusive scan of block sums
__device__ float4 g_pay[2 * MAXE];        // sorted payload: [2p]=rel_q, [2p+1]={w,src,-,-}

// ---------------------------------------------------------------------------
// P1: histogram + rank.  rank[e] = old count of dst[e].
// ---------------------------------------------------------------------------
__global__ void k_hist(const int* __restrict__ edge_dst, int E)
{
    int e = blockIdx.x * blockDim.x + threadIdx.x;
    if (e >= E) return;
    int d = __ldg(edge_dst + e);
    g_rank[e] = atomicAdd(&g_count[d], 1);
}

// ---------------------------------------------------------------------------
// P2a: per-1024-block exclusive scan of g_count; emit block totals.
// ---------------------------------------------------------------------------
__global__ void k_scanA(int N)
{
    int i = blockIdx.x * 1024 + threadIdx.x;
    int lane = threadIdx.x & 31, wid = threadIdx.x >> 5;
    int v = (i < N) ? g_count[i] : 0;
    int x = v;
    #pragma unroll
    for (int o = 1; o < 32; o <<= 1) {
        int y = __shfl_up_sync(0xffffffffu, x, o);
        if (lane >= o) x += y;
    }
    __shared__ int wsum[32];
    if (lane == 31) wsum[wid] = x;
    __syncthreads();
    if (wid == 0) {
        int s = wsum[lane];
        #pragma unroll
        for (int o = 1; o < 32; o <<= 1) {
            int y = __shfl_up_sync(0xffffffffu, s, o);
            if (lane >= o) s += y;
        }
        wsum[lane] = s;
    }
    __syncthreads();
    int incl = x + (wid > 0 ? wsum[wid - 1] : 0);
    if (i < N) g_blocklocal[i] = incl - v;
    if (threadIdx.x == 1023) g_blocksum[blockIdx.x] = incl;
}

// ---------------------------------------------------------------------------
// P2b: exclusive scan of <=128 block sums (single block of 128 threads).
// ---------------------------------------------------------------------------
__global__ void k_scanB(int nb)
{
    int t = threadIdx.x;                  // 128 threads
    int lane = t & 31, wid = t >> 5;
    int v = (t < nb) ? g_blocksum[t] : 0;
    int x = v;
    #pragma unroll
    for (int o = 1; o < 32; o <<= 1) {
        int y = __shfl_up_sync(0xffffffffu, x, o);
        if (lane >= o) x += y;
    }
    __shared__ int wsum[4];
    if (lane == 31) wsum[wid] = x;
    __syncthreads();
    int base = 0;
    for (int wprev = 0; wprev < wid; wprev++) base += wsum[wprev];
    int incl = x + base;
    if (t < nb) g_blockbase[t] = incl - v;
}

// ---------------------------------------------------------------------------
// P2c: materialize g_off[i] = global exclusive prefix; g_off[N] = E.
// ---------------------------------------------------------------------------
__global__ void k_scanC(int N, int E)
{
    int i = blockIdx.x * blockDim.x + threadIdx.x;
    if (i > N) return;
    g_off[i] = (i < N) ? (g_blockbase[i >> 10] + g_blocklocal[i]) : E;
}

// ---------------------------------------------------------------------------
// P3: scatter payload into dst-sorted order (32B aligned stores, no atomics).
// ---------------------------------------------------------------------------
__global__ void k_scatter(const float4* __restrict__ edge_rel_q,
                          const float*  __restrict__ edge_w,
                          const int*    __restrict__ edge_src,
                          const int*    __restrict__ edge_dst,
                          int E)
{
    int e = blockIdx.x * blockDim.x + threadIdx.x;
    if (e >= E) return;
    int d   = __ldg(edge_dst + e);
    int pos = g_off[d] + g_rank[e];
    float4 rq = __ldg(edge_rel_q + e);
    float  w  = __ldg(edge_w + e);
    int    s  = __ldg(edge_src + e);
    g_pay[2 * pos]     = rq;
    g_pay[2 * pos + 1] = make_float4(w, __int_as_float(s), 0.f, 0.f);
}

// ---------------------------------------------------------------------------
// P4: gather-reduce. One warp per node. lane = (j, k): k = lane&7 feature
// index, j = lane>>3 edge-subgroup (4 edges processed in parallel).
// Register accumulation, shfl tree over j, fused self term + normalize.
// ---------------------------------------------------------------------------
__global__ void k_reduce(const float*  __restrict__ node_levels,
                         const float4* __restrict__ node_q,
                         float4* __restrict__ out_q,
                         float*  __restrict__ out_l,
                         int N)
{
    int gw   = (blockIdx.x * blockDim.x + threadIdx.x) >> 5;   // node id
    int lane = threadIdx.x & 31;
    if (gw >= N) return;                                       // whole warp exits
    int k = lane & 7;
    int j = lane >> 3;

    int beg = g_off[gw];
    int end = g_off[gw + 1];

    float aw = 0.f, ax = 0.f, ay = 0.f, az = 0.f, aden = 0.f, al = 0.f;

    for (int i = beg + j; i < end; i += 4) {
        float4 rq = __ldg(&g_pay[2 * i]);          // broadcast across 8 lanes
        float4 ws = __ldg(&g_pay[2 * i + 1]);
        int   s = __float_as_int(ws.y);
        float w = ws.x;

        int si = s * KDIM + k;
        float4 qs = __ldg(node_q + si);            // 128B coalesced per 8 lanes
        float  l  = __ldg(node_levels + si);

        float ee = __expf(8.0f * w * l);           // softmax shift cancels

        // Hamilton product rel_q (*) q_src ; storage (w,x,y,z)
        float w1 = rq.x, x1 = rq.y, y1 = rq.z, z1 = rq.w;
        float w2 = qs.x, x2 = qs.y, y2 = qs.z, z2 = qs.w;
        float ow = w1*w2 - x1*x2 - y1*y2 - z1*z2;
        float ox = w1*x2 + x1*w2 + y1*z2 - z1*y2;
        float oy = w1*y2 - x1*z2 + y1*w2 + z1*x2;
        float oz = w1*z2 + x1*y2 - y1*x2 + z1*w2;

        aw += ee * ow;  ax += ee * ox;  ay += ee * oy;  az += ee * oz;
        aden += ee;     al += ee * l;
    }

    // reduce over j (lanes with equal k are 8 apart): xor 8, xor 16
    #pragma unroll
    for (int o = 8; o < 32; o <<= 1) {
        aw   += __shfl_xor_sync(0xffffffffu, aw,   o);
        ax   += __shfl_xor_sync(0xffffffffu, ax,   o);
        ay   += __shfl_xor_sync(0xffffffffu, ay,   o);
        az   += __shfl_xor_sync(0xffffffffu, az,   o);
        aden += __shfl_xor_sync(0xffffffffu, aden, o);
        al   += __shfl_xor_sync(0xffffffffu, al,   o);
    }

    if (j == 0) {
        int ni = gw * KDIM + k;
        float  l  = __ldg(node_levels + ni);
        float  es = __expf(8.0f * l);              // self term (w = 1)
        float4 q  = __ldg(node_q + ni);

        aw += es * q.x;  ax += es * q.y;  ay += es * q.z;  az += es * q.w;
        aden += es;      al += es * l;

        float inv = 1.0f / aden;
        float qw = aw * inv, qx = ax * inv, qy = ay * inv, qz = az * inv;
        float nrm = sqrtf(qw*qw + qx*qx + qy*qy + qz*qz);
        float r   = 1.0f / fmaxf(nrm, 1e-12f);
        out_q[ni] = make_float4(qw * r, qx * r, qy * r, qz * r);
        out_l[ni] = al * inv;
    }
}

// ---------------------------------------------------------------------------
// Launch. Inputs: 0 node_levels [N,K], 1 node_q [N,K,4], 2 edge_rel_q [E,4],
//                 3 edge_w [E], 4 edge_src [E], 5 edge_dst [E].
// Output: q [N,K,4] flattened, then out_levels [N,K].
// ---------------------------------------------------------------------------
extern "C" void kernel_launch(void* const* d_in, const int* in_sizes, int n_in,
                              void* d_out, int out_size)
{
    const float*  node_levels = (const float*) d_in[0];
    const float4* node_q      = (const float4*)d_in[1];
    const float4* edge_rel_q  = (const float4*)d_in[2];
    const float*  edge_w      = (const float*) d_in[3];
    const int*    edge_src    = (const int*)   d_in[4];
    const int*    edge_dst    = (const int*)   d_in[5];

    int NK = in_sizes[0];
    int N  = NK / KDIM;
    int E  = in_sizes[3];

    float4* out_q = (float4*)d_out;
    float*  out_l = (float*)d_out + (long long)NK * 4;

    void* pCount = nullptr;
    cudaGetSymbolAddress(&pCount, g_count);
    cudaMemsetAsync(pCount, 0, (size_t)N * sizeof(int), 0);

    const int TPB = 256;
    int nb = (N + 1023) / 1024;                    // scan blocks (<=98)

    k_hist   <<<(E + TPB - 1) / TPB, TPB>>>(edge_dst, E);
    k_scanA  <<<nb, 1024>>>(N);
    k_scanB  <<<1, 128>>>(nb);
    k_scanC  <<<(N + 1 + TPB - 1) / TPB, TPB>>>(N, E);
    k_scatter<<<(E + TPB - 1) / TPB, TPB>>>(edge_rel_q, edge_w, edge_src,
                                            edge_dst, E);
    k_reduce <<<(N * 32 + TPB - 1) / TPB, TPB>>>(node_levels, node_q,
                                                 out_q, out_l, N);
}